// round 1
// baseline (speedup 1.0000x reference)
#include <cuda_runtime.h>

#define NN 100000   // nodes
#define NE 300000   // directed edges
#define MT 10000    // tree messages
// All feature dims that matter downstream are 256 (DM = DX = DN = 256), DE = 64.

typedef unsigned long long u64;

// ---------------- scratch (device globals; no allocation allowed) ----------------
__device__ float g_node_h [(size_t)NN * 256];  // f_node @ W1
__device__ float g_base   [(size_t)NE * 256];  // W1 f_src + W2 f_edge + b1 + alpha@W3
__device__ float g_msg    [(size_t)NE * 256];  // msg_2
__device__ float g_y      [(size_t)NE * 256];  // msg @ W3
__device__ float g_agg    [(size_t)NN * 256];  // segment_sum(y, edge_dst)
__device__ float g_nodesum[(size_t)NN * 256];  // segment_sum(msg_final, edge_dst)

// ---------------- packed f32x2 helpers ----------------
__device__ __forceinline__ u64 pk2(float lo, float hi) {
    u64 r; asm("mov.b64 %0, {%1,%2};" : "=l"(r) : "f"(lo), "f"(hi)); return r;
}
__device__ __forceinline__ void upk2(u64 v, float& lo, float& hi) {
    asm("mov.b64 {%0,%1}, %2;" : "=f"(lo), "=f"(hi) : "l"(v));
}
__device__ __forceinline__ void fma2(u64& d, u64 a, u64 b) {
    asm("fma.rn.f32x2 %0, %1, %2, %0;" : "+l"(d) : "l"(a), "l"(b));
}
__device__ __forceinline__ void red4(float* p, float a, float b, float c, float d) {
    asm volatile("red.global.add.v4.f32 [%0], {%1,%2,%3,%4};"
                 :: "l"(p), "f"(a), "f"(b), "f"(c), "f"(d) : "memory");
}

// ---------------- GEMM: C[M,256] = A[M,K] @ B[K,256] (+ epilogue variants) -------
// MODE 0: C = acc                                   (node_h = f_node @ W1)
// MODE 1: C = acc + addmat[gidx[r]] + bias          (base  = f_edge @ W2 + h[src] + b1)
// MODE 2: C[gidx[r]] += acc                         (base[tree_tgt] += tree_msg @ W3)
// MODE 3: C = acc; red aggbuf[gidx[r]] += acc       (y = msg @ W3 ; agg = segsum(y, dst))
// MODE 4: C = acc + bias                            (x  = f_node @ W4 + b2)
// MODE 5: C = relu(C + acc)                         (x  = relu(x + node_sum @ W5))
// RELU_A: apply relu to A elements on load (lets y1-GEMM consume base directly).
template<int MODE, bool RELU_A>
__global__ __launch_bounds__(256, 2)
void gemm128(const float* __restrict__ A, const float* __restrict__ B,
             float* __restrict__ C, int M, int K,
             const float* __restrict__ bias,
             const float* __restrict__ addmat,
             const int*   __restrict__ gidx,
             float*       __restrict__ aggbuf)
{
    __shared__ u64   As2[8][128];   // A values stored as duplicated pairs (a,a)
    __shared__ float Bs [8][128];

    const int tid  = threadIdx.x;
    const int bm   = blockIdx.y * 128;
    const int bn   = blockIdx.x * 128;
    const int aRow = tid >> 1, aCol = (tid & 1) << 2;   // 128 rows x 8 cols, float4 each
    const int bRow = tid >> 5, bCol = (tid & 31) << 2;  // 8 rows x 128 cols, float4 each
    const int ty   = tid >> 4, tx = tid & 15;           // 16x16 threads, 8x8 micro-tile

    u64 acc[8][4];
    #pragma unroll
    for (int i = 0; i < 8; i++)
        #pragma unroll
        for (int j = 0; j < 4; j++) acc[i][j] = 0ull;   // (0.0f, 0.0f)

    int ra = bm + aRow; if (ra >= M) ra = M - 1;        // clamped loads; stores guarded
    const float* Ap = A + (size_t)ra * K;

    for (int k0 = 0; k0 < K; k0 += 8) {
        float4 av = *(const float4*)(Ap + k0 + aCol);
        if (RELU_A) {
            av.x = fmaxf(av.x, 0.f); av.y = fmaxf(av.y, 0.f);
            av.z = fmaxf(av.z, 0.f); av.w = fmaxf(av.w, 0.f);
        }
        As2[aCol + 0][aRow] = pk2(av.x, av.x);
        As2[aCol + 1][aRow] = pk2(av.y, av.y);
        As2[aCol + 2][aRow] = pk2(av.z, av.z);
        As2[aCol + 3][aRow] = pk2(av.w, av.w);
        *(float4*)&Bs[bRow][bCol] =
            *(const float4*)(B + (size_t)(k0 + bRow) * 256 + bn + bCol);
        __syncthreads();

        #pragma unroll
        for (int kk = 0; kk < 8; kk++) {
            const u64* bp = (const u64*)&Bs[kk][tx * 8];
            u64 bb0 = bp[0], bb1 = bp[1], bb2 = bp[2], bb3 = bp[3];
            #pragma unroll
            for (int i = 0; i < 8; i++) {
                u64 ad = As2[kk][ty * 8 + i];
                fma2(acc[i][0], ad, bb0);
                fma2(acc[i][1], ad, bb1);
                fma2(acc[i][2], ad, bb2);
                fma2(acc[i][3], ad, bb3);
            }
        }
        __syncthreads();
    }

    // ---- epilogue ----
    #pragma unroll
    for (int i = 0; i < 8; i++) {
        int r = bm + ty * 8 + i;
        if (r >= M) continue;
        float out[8];
        #pragma unroll
        for (int j = 0; j < 4; j++) upk2(acc[i][j], out[2 * j], out[2 * j + 1]);
        int c0 = bn + tx * 8;

        if constexpr (MODE == 0) {
            *(float4*)(C + (size_t)r * 256 + c0)     = make_float4(out[0], out[1], out[2], out[3]);
            *(float4*)(C + (size_t)r * 256 + c0 + 4) = make_float4(out[4], out[5], out[6], out[7]);
        } else if constexpr (MODE == 1) {
            int g = __ldg(gidx + r);
            const float4* am = (const float4*)(addmat + (size_t)g * 256 + c0);
            const float4* bi = (const float4*)(bias + c0);
            float4 a0 = am[0], a1 = am[1], v0 = bi[0], v1 = bi[1];
            *(float4*)(C + (size_t)r * 256 + c0) =
                make_float4(out[0] + a0.x + v0.x, out[1] + a0.y + v0.y,
                            out[2] + a0.z + v0.z, out[3] + a0.w + v0.w);
            *(float4*)(C + (size_t)r * 256 + c0 + 4) =
                make_float4(out[4] + a1.x + v1.x, out[5] + a1.y + v1.y,
                            out[6] + a1.z + v1.z, out[7] + a1.w + v1.w);
        } else if constexpr (MODE == 2) {
            int ro = __ldg(gidx + r);            // unique targets -> plain RMW is safe
            float4* cp = (float4*)(C + (size_t)ro * 256 + c0);
            float4 o0 = cp[0], o1 = cp[1];
            cp[0] = make_float4(o0.x + out[0], o0.y + out[1], o0.z + out[2], o0.w + out[3]);
            cp[1] = make_float4(o1.x + out[4], o1.y + out[5], o1.z + out[6], o1.w + out[7]);
        } else if constexpr (MODE == 3) {
            *(float4*)(C + (size_t)r * 256 + c0)     = make_float4(out[0], out[1], out[2], out[3]);
            *(float4*)(C + (size_t)r * 256 + c0 + 4) = make_float4(out[4], out[5], out[6], out[7]);
            int d = __ldg(gidx + r);
            float* ap = aggbuf + (size_t)d * 256 + c0;
            red4(ap,     out[0], out[1], out[2], out[3]);
            red4(ap + 4, out[4], out[5], out[6], out[7]);
        } else if constexpr (MODE == 4) {
            const float4* bi = (const float4*)(bias + c0);
            float4 v0 = bi[0], v1 = bi[1];
            *(float4*)(C + (size_t)r * 256 + c0) =
                make_float4(out[0] + v0.x, out[1] + v0.y, out[2] + v0.z, out[3] + v0.w);
            *(float4*)(C + (size_t)r * 256 + c0 + 4) =
                make_float4(out[4] + v1.x, out[5] + v1.y, out[6] + v1.z, out[7] + v1.w);
        } else if constexpr (MODE == 5) {
            float4* cp = (float4*)(C + (size_t)r * 256 + c0);
            float4 o0 = cp[0], o1 = cp[1];
            cp[0] = make_float4(fmaxf(o0.x + out[0], 0.f), fmaxf(o0.y + out[1], 0.f),
                                fmaxf(o0.z + out[2], 0.f), fmaxf(o0.w + out[3], 0.f));
            cp[1] = make_float4(fmaxf(o1.x + out[4], 0.f), fmaxf(o1.y + out[5], 0.f),
                                fmaxf(o1.z + out[6], 0.f), fmaxf(o1.w + out[7], 0.f));
        }
    }
}

// ---------------- combine: msg = relu(base + agg[src] - y[e^1]) ----------------
// FINAL=true: do not materialize msg; scatter-add it into node_sum instead.
template<bool FINAL>
__global__ __launch_bounds__(256)
void combine_k(const float* __restrict__ base, const float* __restrict__ agg,
               const float* __restrict__ y,    const int* __restrict__ esrc,
               const int* __restrict__ edst,
               float* __restrict__ msg, float* __restrict__ nodesum)
{
    int gid = blockIdx.x * blockDim.x + threadIdx.x;   // NE*64 float4-threads
    if (gid >= NE * 64) return;
    int e = gid >> 6;
    int c = (gid & 63) << 2;
    int s = __ldg(esrc + e);
    float4 b  = *(const float4*)(base + (size_t)e * 256 + c);
    float4 a  = *(const float4*)(agg  + (size_t)s * 256 + c);
    float4 yr = *(const float4*)(y    + (size_t)(e ^ 1) * 256 + c);
    float4 m;
    m.x = fmaxf(b.x + a.x - yr.x, 0.f);
    m.y = fmaxf(b.y + a.y - yr.y, 0.f);
    m.z = fmaxf(b.z + a.z - yr.z, 0.f);
    m.w = fmaxf(b.w + a.w - yr.w, 0.f);
    if (FINAL) {
        int d = __ldg(edst + e);
        red4(nodesum + (size_t)d * 256 + c, m.x, m.y, m.z, m.w);
    } else {
        *(float4*)(msg + (size_t)e * 256 + c) = m;
    }
}

__global__ void zero_k(float* __restrict__ p, int n4)
{
    int i = blockIdx.x * blockDim.x + threadIdx.x;
    if (i < n4) ((float4*)p)[i] = make_float4(0.f, 0.f, 0.f, 0.f);
}

// --------------------------------- launch ---------------------------------
extern "C" void kernel_launch(void* const* d_in, const int* in_sizes, int n_in,
                              void* d_out, int out_size)
{
    const float* f_node   = (const float*)d_in[0];
    const float* f_edge   = (const float*)d_in[1];
    const float* tree_msg = (const float*)d_in[2];
    const float* W1       = (const float*)d_in[3];
    const float* W2       = (const float*)d_in[4];
    const float* W3       = (const float*)d_in[5];
    const float* b1       = (const float*)d_in[6];
    const float* W4       = (const float*)d_in[7];
    const float* W5       = (const float*)d_in[8];
    const float* b2       = (const float*)d_in[9];
    const int* edge_src   = (const int*)d_in[10];
    const int* edge_dst   = (const int*)d_in[11];
    const int* tree_tgt   = (const int*)d_in[12];
    float* out = (float*)d_out;

    float *node_h, *base, *msg, *y, *agg, *nodesum;
    cudaGetSymbolAddress((void**)&node_h,  g_node_h);
    cudaGetSymbolAddress((void**)&base,    g_base);
    cudaGetSymbolAddress((void**)&msg,     g_msg);
    cudaGetSymbolAddress((void**)&y,       g_y);
    cudaGetSymbolAddress((void**)&agg,     g_agg);
    cudaGetSymbolAddress((void**)&nodesum, g_nodesum);

    const dim3 blk(256);
    const dim3 gN (2, (NN + 127) / 128);   // node-level GEMMs
    const dim3 gE (2, (NE + 127) / 128);   // edge-level GEMMs
    const dim3 gT (2, (MT + 127) / 128);   // tree GEMM
    const int  zeroGrid = (NN * 64 + 255) / 256;
    const int  combGrid = (NE * 64 + 255) / 256;

    // 1) node_h = f_node @ W1
    gemm128<0, false><<<gN, blk>>>(f_node, W1, node_h, NN, 256, nullptr, nullptr, nullptr, nullptr);
    // 2) base = f_edge @ W2 + node_h[edge_src] + b1
    gemm128<1, false><<<gE, blk>>>(f_edge, W2, base, NE, 64, b1, node_h, edge_src, nullptr);
    // 3) base[tree_tgt] += tree_msg @ W3   (fold alpha@W3 into base)
    gemm128<2, false><<<gT, blk>>>(tree_msg, W3, base, MT, 256, nullptr, nullptr, tree_tgt, nullptr);

    // iter 1 is msg1 = relu(base); fuse relu into y1 GEMM's A-load.
    // 4) agg = 0 ; 5) y1 = relu(base) @ W3, agg[dst] += y1
    zero_k<<<zeroGrid, blk>>>(agg, NN * 64);
    gemm128<3, true><<<gE, blk>>>(base, W3, y, NE, 256, nullptr, nullptr, edge_dst, agg);
    // 6) msg2 = relu(base + agg[src] - y1[rev])
    combine_k<false><<<combGrid, blk>>>(base, agg, y, edge_src, edge_dst, msg, nullptr);

    // 7) agg = 0 ; 8) y2 = msg2 @ W3, agg[dst] += y2
    zero_k<<<zeroGrid, blk>>>(agg, NN * 64);
    gemm128<3, false><<<gE, blk>>>(msg, W3, y, NE, 256, nullptr, nullptr, edge_dst, agg);
    // 9) node_sum = 0 ; 10) msg3 = relu(base + agg[src] - y2[rev]); node_sum[dst] += msg3
    zero_k<<<zeroGrid, blk>>>(nodesum, NN * 64);
    combine_k<true><<<combGrid, blk>>>(base, agg, y, edge_src, edge_dst, nullptr, nodesum);

    // 11) out = f_node @ W4 + b2 ; 12) out = relu(out + node_sum @ W5)
    gemm128<4, false><<<gN, blk>>>(f_node, W4, out, NN, 256, b2, nullptr, nullptr, nullptr);
    gemm128<5, false><<<gN, blk>>>(nodesum, W5, out, NN, 256, nullptr, nullptr, nullptr, nullptr);
}

// round 3
// speedup vs baseline: 2.0408x; 2.0408x over previous
#include <cuda_runtime.h>
#include <cuda_bf16.h>
#include <cstdint>

#define NN 100000
#define NE 300000
#define MT 10000

typedef unsigned long long u64;
typedef unsigned int u32;
typedef __nv_bfloat16 bf16;

// ---------------- scratch (device globals; no allocation allowed) ----------------
__device__ float g_node_h [(size_t)NN*256];
__device__ float g_base   [(size_t)NE*256];
__device__ float g_y      [(size_t)NE*256];
__device__ float g_agg    [(size_t)NN*256];
__device__ float g_nodesum[(size_t)NN*256];
// bf16 hi/lo split buffers
__device__ bf16 g_fn_h[(size_t)NN*256], g_fn_l[(size_t)NN*256];   // f_node split
__device__ bf16 g_fe_h[(size_t)NE*64],  g_fe_l[(size_t)NE*64];    // f_edge split
__device__ bf16 g_tm_h[(size_t)MT*256], g_tm_l[(size_t)MT*256];   // tree_msg split
__device__ bf16 g_a_h [(size_t)NE*256], g_a_l [(size_t)NE*256];   // relu(base)/msg/nodesum splits
// B matrices transposed+split: B[n][k] = W[k][n]
__device__ bf16 g_B1h[256*256], g_B1l[256*256];
__device__ bf16 g_B2h[256*64],  g_B2l[256*64];
__device__ bf16 g_B3h[256*256], g_B3l[256*256];
__device__ bf16 g_B4h[256*256], g_B4l[256*256];
__device__ bf16 g_B5h[256*256], g_B5l[256*256];

// ---------------- helpers ----------------
__device__ __forceinline__ u32 smem_u32(const void* p) {
    u32 a; asm("{ .reg .u64 t; cvta.to.shared.u64 t, %1; cvt.u32.u64 %0, t; }" : "=r"(a) : "l"(p));
    return a;
}
__device__ __forceinline__ void cp16(u32 dst, const void* src) {
    asm volatile("cp.async.cg.shared.global [%0], [%1], 16;" :: "r"(dst), "l"(src));
}
__device__ __forceinline__ void red2(float* p, float a, float b) {
    asm volatile("red.global.add.v2.f32 [%0], {%1,%2};" :: "l"(p), "f"(a), "f"(b) : "memory");
}
__device__ __forceinline__ void red4(float* p, float a, float b, float c, float d) {
    asm volatile("red.global.add.v4.f32 [%0], {%1,%2,%3,%4};"
                 :: "l"(p), "f"(a), "f"(b), "f"(c), "f"(d) : "memory");
}
__device__ __forceinline__ void ldsm4(u32* r, u32 addr) {
    asm volatile("ldmatrix.sync.aligned.m8n8.x4.shared.b16 {%0,%1,%2,%3}, [%4];"
                 : "=r"(r[0]), "=r"(r[1]), "=r"(r[2]), "=r"(r[3]) : "r"(addr));
}
__device__ __forceinline__ void mma16816(float* d, const u32* a, const u32* b) {
    asm volatile("mma.sync.aligned.m16n8k16.row.col.f32.bf16.bf16.f32 "
                 "{%0,%1,%2,%3}, {%4,%5,%6,%7}, {%8,%9}, {%0,%1,%2,%3};"
                 : "+f"(d[0]), "+f"(d[1]), "+f"(d[2]), "+f"(d[3])
                 : "r"(a[0]), "r"(a[1]), "r"(a[2]), "r"(a[3]), "r"(b[0]), "r"(b[1]));
}
__device__ __forceinline__ void split_store2(bf16* hp, bf16* lp, float x, float y) {
    bf16 hx = __float2bfloat16(x), hy = __float2bfloat16(y);
    __nv_bfloat162 h2; h2.x = hx; h2.y = hy;
    *(__nv_bfloat162*)hp = h2;
    __nv_bfloat162 l2;
    l2.x = __float2bfloat16(x - __bfloat162float(hx));
    l2.y = __float2bfloat16(y - __bfloat162float(hy));
    *(__nv_bfloat162*)lp = l2;
}
__device__ __forceinline__ void split_store4(bf16* hp, bf16* lp, float4 v) {
    split_store2(hp, lp, v.x, v.y);
    split_store2(hp + 2, lp + 2, v.z, v.w);
}

// smem: 2 stages x [AH | AL | BH | BL], each buffer 128 rows x 80 bytes = 10240 B
#define BUF_BYTES 10240u
#define STAGE_BYTES (4u * BUF_BYTES)
#define SM_BYTES (2 * STAGE_BYTES)       // 81920

// ------------------- mma.sync GEMM: C[M,256] = A[M,K] @ W[K,256] -------------------
// Split-bf16 3-term: Ah@Bh + Ah@Bl + Al@Bh, fp32 accumulate.
// MODE 0: C = acc
// MODE 1: C = acc + addmat[gidx[r]] + bias; also write relu-split to rh/rl
// MODE 2: C[gidx[r]] += acc; re-write relu-split of that row
// MODE 3: C = acc; red agg[gidx[r]] += acc
// MODE 4: C = acc + bias
// MODE 5: C = relu(C + acc)
template<int MODE>
__global__ __launch_bounds__(256)
void tgemm(const bf16* __restrict__ Ah, const bf16* __restrict__ Al,
           const bf16* __restrict__ Bh, const bf16* __restrict__ Bl,
           float* __restrict__ C, int M, int K,
           const float* __restrict__ bias, const float* __restrict__ addmat,
           const int* __restrict__ gidx, float* __restrict__ agg,
           bf16* __restrict__ rh, bf16* __restrict__ rl)
{
    extern __shared__ char smem[];
    const u32 sb = smem_u32(smem);
    const int tid  = threadIdx.x;
    const int lane = tid & 31, w = tid >> 5;
    const int wm = w >> 2, wn = w & 3;          // 2 x 4 warp grid
    const int bm = blockIdx.y * 128;
    const int bn = blockIdx.x * 128;
    const int chunks = K >> 5;                   // BK = 32

    float acc[4][4][4];
    #pragma unroll
    for (int i = 0; i < 4; i++)
        #pragma unroll
        for (int j = 0; j < 4; j++)
            #pragma unroll
            for (int q = 0; q < 4; q++) acc[i][j][q] = 0.f;

    // per-thread load coords: A/B row = tid>>1 (0..127), 2x16B chunks at ch*8 elems
    const int lr = tid >> 1;
    const int ch = (tid & 1) * 2;
    int growA = bm + lr; if (growA >= M) growA = M - 1;
    const u32 so = (u32)lr * 80u + (u32)ch * 16u;

    auto load_chunk = [&](int c, int s) {
        const u32 base = sb + (u32)s * STAGE_BYTES;
        const size_t gbA = ((size_t)growA * K + c * 32 + ch * 8) * 2;
        const size_t gbB = ((size_t)(bn + lr) * K + c * 32 + ch * 8) * 2;
        cp16(base + so,                  (const char*)Ah + gbA);
        cp16(base + so + 16,             (const char*)Ah + gbA + 16);
        cp16(base + BUF_BYTES + so,      (const char*)Al + gbA);
        cp16(base + BUF_BYTES + so + 16, (const char*)Al + gbA + 16);
        cp16(base + 2*BUF_BYTES + so,      (const char*)Bh + gbB);
        cp16(base + 2*BUF_BYTES + so + 16, (const char*)Bh + gbB + 16);
        cp16(base + 3*BUF_BYTES + so,      (const char*)Bl + gbB);
        cp16(base + 3*BUF_BYTES + so + 16, (const char*)Bl + gbB + 16);
    };

    // per-lane ldmatrix address bases (byte offsets within a buffer)
    const u32 aAddr = (u32)(wm * 64 + (lane & 15)) * 80u + (u32)(lane >> 4) * 16u;
    const u32 bAddr = (u32)(wn * 32 + ((lane >> 4) << 3) + (lane & 7)) * 80u
                    + (u32)((lane >> 3) & 1) * 16u;

    load_chunk(0, 0);
    asm volatile("cp.async.commit_group;" ::: "memory");

    for (int c = 0; c < chunks; c++) {
        const int s = c & 1;
        if (c + 1 < chunks) {
            load_chunk(c + 1, (c + 1) & 1);
            asm volatile("cp.async.commit_group;" ::: "memory");
            asm volatile("cp.async.wait_group 1;" ::: "memory");
        } else {
            asm volatile("cp.async.wait_group 0;" ::: "memory");
        }
        __syncthreads();

        const u32 stage = sb + (u32)s * STAGE_BYTES;
        #pragma unroll
        for (int t = 0; t < 3; t++) {
            const u32 sA = stage + ((t < 2) ? 0u : BUF_BYTES) + aAddr;
            const u32 sB = stage + ((t == 1) ? 3u : 2u) * BUF_BYTES + bAddr;
            #pragma unroll
            for (int ks = 0; ks < 2; ks++) {
                u32 af[4][4], bf_[2][4];
                #pragma unroll
                for (int mt = 0; mt < 4; mt++)
                    ldsm4(af[mt], sA + (u32)mt * (16u * 80u) + (u32)ks * 32u);
                #pragma unroll
                for (int p = 0; p < 2; p++)
                    ldsm4(bf_[p], sB + (u32)p * (16u * 80u) + (u32)ks * 32u);
                #pragma unroll
                for (int mt = 0; mt < 4; mt++)
                    #pragma unroll
                    for (int nt = 0; nt < 4; nt++)
                        mma16816(acc[mt][nt], af[mt], &bf_[nt >> 1][(nt & 1) * 2]);
            }
        }
        __syncthreads();
    }

    // ---------------- epilogue ----------------
    #pragma unroll
    for (int mt = 0; mt < 4; mt++) {
        #pragma unroll
        for (int half = 0; half < 2; half++) {
            const int r = bm + wm * 64 + mt * 16 + (lane >> 2) + half * 8;
            if (r >= M) continue;
            int g = 0;
            if (MODE == 1 || MODE == 2 || MODE == 3) g = __ldg(gidx + r);
            const size_t rowC = (size_t)r * 256;
            #pragma unroll
            for (int nt = 0; nt < 4; nt++) {
                const int c0 = bn + wn * 32 + nt * 8 + (lane & 3) * 2;
                float vx = acc[mt][nt][2 * half], vy = acc[mt][nt][2 * half + 1];
                if constexpr (MODE == 0) {
                    *(float2*)(C + rowC + c0) = make_float2(vx, vy);
                } else if constexpr (MODE == 1) {
                    const float2 ad = *(const float2*)(addmat + (size_t)g * 256 + c0);
                    const float2 bi = *(const float2*)(bias + c0);
                    vx += ad.x + bi.x; vy += ad.y + bi.y;
                    *(float2*)(C + rowC + c0) = make_float2(vx, vy);
                    split_store2(rh + rowC + c0, rl + rowC + c0,
                                 fmaxf(vx, 0.f), fmaxf(vy, 0.f));
                } else if constexpr (MODE == 2) {
                    const size_t rowG = (size_t)g * 256;
                    float2 bs = *(float2*)(C + rowG + c0);
                    bs.x += vx; bs.y += vy;
                    *(float2*)(C + rowG + c0) = bs;
                    split_store2(rh + rowG + c0, rl + rowG + c0,
                                 fmaxf(bs.x, 0.f), fmaxf(bs.y, 0.f));
                } else if constexpr (MODE == 3) {
                    *(float2*)(C + rowC + c0) = make_float2(vx, vy);
                    red2(agg + (size_t)g * 256 + c0, vx, vy);
                } else if constexpr (MODE == 4) {
                    const float2 bi = *(const float2*)(bias + c0);
                    *(float2*)(C + rowC + c0) = make_float2(vx + bi.x, vy + bi.y);
                } else if constexpr (MODE == 5) {
                    float2 o = *(float2*)(C + rowC + c0);
                    o.x = fmaxf(o.x + vx, 0.f); o.y = fmaxf(o.y + vy, 0.f);
                    *(float2*)(C + rowC + c0) = o;
                }
            }
        }
    }
}

// ---------------- elementwise kernels ----------------
__global__ void split_k(const float* __restrict__ x, bf16* __restrict__ h,
                        bf16* __restrict__ l, int n4)
{
    int i = blockIdx.x * blockDim.x + threadIdx.x;
    if (i >= n4) return;
    float4 v = ((const float4*)x)[i];
    split_store4(h + (size_t)i * 4, l + (size_t)i * 4, v);
}

__global__ void splitBT_k(const float* __restrict__ W, bf16* __restrict__ h,
                          bf16* __restrict__ l, int K)
{
    int i = blockIdx.x * blockDim.x + threadIdx.x;   // B[n][k] = W[k][n]
    if (i >= 256 * K) return;
    int n = i / K, k = i % K;
    float v = W[(size_t)k * 256 + n];
    bf16 hi = __float2bfloat16(v);
    h[i] = hi;
    l[i] = __float2bfloat16(v - __bfloat162float(hi));
}

// combine: m = relu(base + agg[src] - y[e^1]); MID: bf16 split; FINAL: red into nodesum
template<bool FINAL>
__global__ __launch_bounds__(256)
void combine_k(const float* __restrict__ base, const float* __restrict__ agg,
               const float* __restrict__ y, const int* __restrict__ esrc,
               const int* __restrict__ edst,
               bf16* __restrict__ mh, bf16* __restrict__ ml, float* __restrict__ nodesum)
{
    int gid = blockIdx.x * blockDim.x + threadIdx.x;
    if (gid >= NE * 64) return;
    int e = gid >> 6;
    int c = (gid & 63) << 2;
    int s = __ldg(esrc + e);
    float4 b  = *(const float4*)(base + (size_t)e * 256 + c);
    float4 a  = *(const float4*)(agg  + (size_t)s * 256 + c);
    float4 yr = *(const float4*)(y    + (size_t)(e ^ 1) * 256 + c);
    float4 m;
    m.x = fmaxf(b.x + a.x - yr.x, 0.f);
    m.y = fmaxf(b.y + a.y - yr.y, 0.f);
    m.z = fmaxf(b.z + a.z - yr.z, 0.f);
    m.w = fmaxf(b.w + a.w - yr.w, 0.f);
    if (FINAL) {
        int d = __ldg(edst + e);
        red4(nodesum + (size_t)d * 256 + c, m.x, m.y, m.z, m.w);
    } else {
        split_store4(mh + (size_t)e * 256 + c, ml + (size_t)e * 256 + c, m);
    }
}

__global__ void zero_k(float* __restrict__ p, int n4)
{
    int i = blockIdx.x * blockDim.x + threadIdx.x;
    if (i < n4) ((float4*)p)[i] = make_float4(0.f, 0.f, 0.f, 0.f);
}

// --------------------------------- launch ---------------------------------
extern "C" void kernel_launch(void* const* d_in, const int* in_sizes, int n_in,
                              void* d_out, int out_size)
{
    const float* f_node   = (const float*)d_in[0];
    const float* f_edge   = (const float*)d_in[1];
    const float* tree_msg = (const float*)d_in[2];
    const float* W1       = (const float*)d_in[3];
    const float* W2       = (const float*)d_in[4];
    const float* W3       = (const float*)d_in[5];
    const float* b1       = (const float*)d_in[6];
    const float* W4       = (const float*)d_in[7];
    const float* W5       = (const float*)d_in[8];
    const float* b2       = (const float*)d_in[9];
    const int* edge_src   = (const int*)d_in[10];
    const int* edge_dst   = (const int*)d_in[11];
    const int* tree_tgt   = (const int*)d_in[12];
    float* out = (float*)d_out;

    float *node_h, *base, *y, *agg, *nodesum;
    bf16 *fnh, *fnl, *feh, *fel, *tmh, *tml, *ah, *al;
    bf16 *B1h, *B1l, *B2h, *B2l, *B3h, *B3l, *B4h, *B4l, *B5h, *B5l;
    cudaGetSymbolAddress((void**)&node_h,  g_node_h);
    cudaGetSymbolAddress((void**)&base,    g_base);
    cudaGetSymbolAddress((void**)&y,       g_y);
    cudaGetSymbolAddress((void**)&agg,     g_agg);
    cudaGetSymbolAddress((void**)&nodesum, g_nodesum);
    cudaGetSymbolAddress((void**)&fnh, g_fn_h); cudaGetSymbolAddress((void**)&fnl, g_fn_l);
    cudaGetSymbolAddress((void**)&feh, g_fe_h); cudaGetSymbolAddress((void**)&fel, g_fe_l);
    cudaGetSymbolAddress((void**)&tmh, g_tm_h); cudaGetSymbolAddress((void**)&tml, g_tm_l);
    cudaGetSymbolAddress((void**)&ah,  g_a_h);  cudaGetSymbolAddress((void**)&al,  g_a_l);
    cudaGetSymbolAddress((void**)&B1h, g_B1h);  cudaGetSymbolAddress((void**)&B1l, g_B1l);
    cudaGetSymbolAddress((void**)&B2h, g_B2h);  cudaGetSymbolAddress((void**)&B2l, g_B2l);
    cudaGetSymbolAddress((void**)&B3h, g_B3h);  cudaGetSymbolAddress((void**)&B3l, g_B3l);
    cudaGetSymbolAddress((void**)&B4h, g_B4h);  cudaGetSymbolAddress((void**)&B4l, g_B4l);
    cudaGetSymbolAddress((void**)&B5h, g_B5h);  cudaGetSymbolAddress((void**)&B5l, g_B5l);

    cudaFuncSetAttribute(tgemm<0>, cudaFuncAttributeMaxDynamicSharedMemorySize, SM_BYTES);
    cudaFuncSetAttribute(tgemm<1>, cudaFuncAttributeMaxDynamicSharedMemorySize, SM_BYTES);
    cudaFuncSetAttribute(tgemm<2>, cudaFuncAttributeMaxDynamicSharedMemorySize, SM_BYTES);
    cudaFuncSetAttribute(tgemm<3>, cudaFuncAttributeMaxDynamicSharedMemorySize, SM_BYTES);
    cudaFuncSetAttribute(tgemm<4>, cudaFuncAttributeMaxDynamicSharedMemorySize, SM_BYTES);
    cudaFuncSetAttribute(tgemm<5>, cudaFuncAttributeMaxDynamicSharedMemorySize, SM_BYTES);

    const dim3 blk(256);
    const int zeroGrid = (NN * 64 + 255) / 256;
    const int combGrid = (NE * 64 + 255) / 256;
    const dim3 gN(2, (NN + 127) / 128);
    const dim3 gE(2, (NE + 127) / 128);
    const dim3 gT(2, (MT + 127) / 128);

    // ---- pre-split weights (transposed) and A inputs ----
    splitBT_k<<<(256*256+255)/256, blk>>>(W1, B1h, B1l, 256);
    splitBT_k<<<(256*64 +255)/256, blk>>>(W2, B2h, B2l, 64);
    splitBT_k<<<(256*256+255)/256, blk>>>(W3, B3h, B3l, 256);
    splitBT_k<<<(256*256+255)/256, blk>>>(W4, B4h, B4l, 256);
    splitBT_k<<<(256*256+255)/256, blk>>>(W5, B5h, B5l, 256);
    split_k<<<(NN*64+255)/256, blk>>>(f_node,   fnh, fnl, NN*64);
    split_k<<<(NE*16+255)/256, blk>>>(f_edge,   feh, fel, NE*16);
    split_k<<<(MT*64+255)/256, blk>>>(tree_msg, tmh, tml, MT*64);

    // ---- node_h = f_node @ W1 ----
    tgemm<0><<<gN, blk, SM_BYTES>>>(fnh, fnl, B1h, B1l, node_h, NN, 256,
                                    nullptr, nullptr, nullptr, nullptr, nullptr, nullptr);
    // ---- base = f_edge @ W2 + node_h[src] + b1 ; write relu-split(ah/al) ----
    tgemm<1><<<gE, blk, SM_BYTES>>>(feh, fel, B2h, B2l, base, NE, 64,
                                    b1, node_h, edge_src, nullptr, ah, al);
    // ---- base[tree_tgt] += tree_msg @ W3 ; patch relu-split rows ----
    tgemm<2><<<gT, blk, SM_BYTES>>>(tmh, tml, B3h, B3l, base, MT, 256,
                                    nullptr, nullptr, tree_tgt, nullptr, ah, al);

    // ---- iter 1: y1 = relu(base) @ W3 ; agg = segsum(y1, dst) ----
    zero_k<<<zeroGrid, blk>>>(agg, NN * 64);
    tgemm<3><<<gE, blk, SM_BYTES>>>(ah, al, B3h, B3l, y, NE, 256,
                                    nullptr, nullptr, edge_dst, agg, nullptr, nullptr);
    // ---- msg2 = relu(base + agg[src] - y1[rev]) -> bf16 split ----
    combine_k<false><<<combGrid, blk>>>(base, agg, y, edge_src, edge_dst, ah, al, nullptr);

    // ---- iter 2: y2 = msg2 @ W3 ; agg = segsum(y2, dst) ----
    zero_k<<<zeroGrid, blk>>>(agg, NN * 64);
    tgemm<3><<<gE, blk, SM_BYTES>>>(ah, al, B3h, B3l, y, NE, 256,
                                    nullptr, nullptr, edge_dst, agg, nullptr, nullptr);
    // ---- iter 3 fused with readout reduce ----
    zero_k<<<zeroGrid, blk>>>(nodesum, NN * 64);
    combine_k<true><<<combGrid, blk>>>(base, agg, y, edge_src, edge_dst, nullptr, nullptr, nodesum);

    // ---- readout: out = relu(f_node @ W4 + node_sum @ W5 + b2) ----
    split_k<<<(NN*64+255)/256, blk>>>(nodesum, ah, al, NN*64);
    tgemm<4><<<gN, blk, SM_BYTES>>>(fnh, fnl, B4h, B4l, out, NN, 256,
                                    b2, nullptr, nullptr, nullptr, nullptr, nullptr);
    tgemm<5><<<gN, blk, SM_BYTES>>>(ah, al, B5h, B5l, out, NN, 256,
                                    nullptr, nullptr, nullptr, nullptr, nullptr, nullptr);
}